// round 1
// baseline (speedup 1.0000x reference)
#include <cuda_runtime.h>
#include <cstdint>

// Problem constants
#define SEQ   2048
#define DDIM  64
#define NBH   64          // B*H = 4*16
#define BM    128         // queries per CTA
#define BN    64          // keys per iteration
#define NWARP 8
#define NTHR  256
#define NITER (SEQ / BN)  // 32

// Shared memory strides (floats), chosen for conflict-free fragment loads:
//  K B-frag addr = (j*8+g)*KSTR + kk*8 + t  -> bank (g*KSTR + t)%32, KSTR%32==4 -> distinct
//  V B-frag addr = (kk*8+t)*VSTR + j*8 + g  -> bank (t*VSTR + g)%32, VSTR%32==8 -> distinct
//  P A-frag addr = g*PSTR + kk*8 + t        -> same as K pattern
#define KSTR 68
#define VSTR 72
#define PSTR 68
#define SK_OFF 0
#define SV_OFF (64 * KSTR)                 // 4352
#define SP_OFF (SV_OFF + 64 * VSTR)        // 8960
#define SMEM_FLOATS (SP_OFF + NWARP * 16 * PSTR)   // 17664 floats
#define SMEM_BYTES (SMEM_FLOATS * 4)               // 70656 bytes

__device__ __forceinline__ unsigned f2tf(float x) {
    unsigned r;
    asm("cvt.rna.tf32.f32 %0, %1;" : "=r"(r) : "f"(x));
    return r;
}

__device__ __forceinline__ void mma_tf32(float c[4],
                                         unsigned a0, unsigned a1, unsigned a2, unsigned a3,
                                         unsigned b0, unsigned b1) {
    asm volatile(
        "mma.sync.aligned.m16n8k8.row.col.f32.tf32.tf32.f32 "
        "{%0,%1,%2,%3}, {%4,%5,%6,%7}, {%8,%9}, {%0,%1,%2,%3};\n"
        : "+f"(c[0]), "+f"(c[1]), "+f"(c[2]), "+f"(c[3])
        : "r"(a0), "r"(a1), "r"(a2), "r"(a3), "r"(b0), "r"(b1));
}

__global__ void __launch_bounds__(NTHR, 1)
sdpa_tf32_kernel(const float* __restrict__ Q, const float* __restrict__ K,
                 const float* __restrict__ V, float* __restrict__ O) {
    extern __shared__ float sm[];
    float* sK = sm + SK_OFF;
    float* sV = sm + SV_OFF;

    const int tid  = threadIdx.x;
    const int warp = tid >> 5;
    const int lane = tid & 31;
    const int g = lane >> 2;   // group id (0..7)
    const int t = lane & 3;    // thread in group (0..3)
    float* sP = sm + SP_OFF + warp * 16 * PSTR;

    const int bh = blockIdx.y;
    const int qb = blockIdx.x;
    const float* Qb = Q + (size_t)bh * SEQ * DDIM;
    const float* Kb = K + (size_t)bh * SEQ * DDIM;
    const float* Vb = V + (size_t)bh * SEQ * DDIM;
    float*       Ob = O + (size_t)bh * SEQ * DDIM;

    const int qrow = qb * BM + warp * 16 + g;   // rows qrow and qrow+8

    // Load Q fragments: scale by 1/sqrt(D) * log2(e) so softmax is in exp2 domain.
    const float QSCALE = 0.125f * 1.4426950408889634f;
    unsigned qf[8][4];
#pragma unroll
    for (int kk = 0; kk < 8; kk++) {
        const int c0 = kk * 8 + t;
        qf[kk][0] = f2tf(Qb[(size_t)qrow * DDIM + c0]       * QSCALE);
        qf[kk][1] = f2tf(Qb[(size_t)(qrow + 8) * DDIM + c0] * QSCALE);
        qf[kk][2] = f2tf(Qb[(size_t)qrow * DDIM + c0 + 4]       * QSCALE);
        qf[kk][3] = f2tf(Qb[(size_t)(qrow + 8) * DDIM + c0 + 4] * QSCALE);
    }

    float o[8][4];
#pragma unroll
    for (int j = 0; j < 8; j++) { o[j][0] = o[j][1] = o[j][2] = o[j][3] = 0.f; }
    float m0 = -1e30f, m1 = -1e30f, l0 = 0.f, l1 = 0.f;

    for (int kb = 0; kb < NITER; kb++) {
        __syncthreads();   // all warps done reading prior sK/sV

        // Cooperative K/V tile load, tf32-rounded at store. 64x64 floats = 1024 float4.
        const float* Kt = Kb + (size_t)kb * BN * DDIM;
        const float* Vt = Vb + (size_t)kb * BN * DDIM;
#pragma unroll
        for (int it = 0; it < 4; it++) {
            const int f4  = tid + it * NTHR;      // 0..1023
            const int row = f4 >> 4;
            const int c4  = (f4 & 15) * 4;
            float4 kv = *(const float4*)(Kt + row * DDIM + c4);
            float4 vv = *(const float4*)(Vt + row * DDIM + c4);
            float4 ko = make_float4(__uint_as_float(f2tf(kv.x)), __uint_as_float(f2tf(kv.y)),
                                    __uint_as_float(f2tf(kv.z)), __uint_as_float(f2tf(kv.w)));
            float4 vo = make_float4(__uint_as_float(f2tf(vv.x)), __uint_as_float(f2tf(vv.y)),
                                    __uint_as_float(f2tf(vv.z)), __uint_as_float(f2tf(vv.w)));
            *(float4*)(sK + row * KSTR + c4) = ko;
            *(float4*)(sV + row * VSTR + c4) = vo;
        }
        __syncthreads();

        // ---- S = Q * K^T  (per warp: 16 x 64 scores) ----
        float s[8][4];
#pragma unroll
        for (int j = 0; j < 8; j++) { s[j][0] = s[j][1] = s[j][2] = s[j][3] = 0.f; }
#pragma unroll
        for (int kk = 0; kk < 8; kk++) {
#pragma unroll
            for (int j = 0; j < 8; j++) {
                const int base = (j * 8 + g) * KSTR + kk * 8 + t;
                unsigned b0 = __float_as_uint(sK[base]);
                unsigned b1 = __float_as_uint(sK[base + 4]);
                mma_tf32(s[j], qf[kk][0], qf[kk][1], qf[kk][2], qf[kk][3], b0, b1);
            }
        }

        // ---- online softmax (exp2 domain) ----
        float mt0 = -1e30f, mt1 = -1e30f;
#pragma unroll
        for (int j = 0; j < 8; j++) {
            mt0 = fmaxf(mt0, fmaxf(s[j][0], s[j][1]));
            mt1 = fmaxf(mt1, fmaxf(s[j][2], s[j][3]));
        }
        mt0 = fmaxf(mt0, __shfl_xor_sync(0xffffffffu, mt0, 1));
        mt0 = fmaxf(mt0, __shfl_xor_sync(0xffffffffu, mt0, 2));
        mt1 = fmaxf(mt1, __shfl_xor_sync(0xffffffffu, mt1, 1));
        mt1 = fmaxf(mt1, __shfl_xor_sync(0xffffffffu, mt1, 2));

        const float mn0 = fmaxf(m0, mt0);
        const float mn1 = fmaxf(m1, mt1);
        const float fac0 = exp2f(m0 - mn0);
        const float fac1 = exp2f(m1 - mn1);

        float rs0 = 0.f, rs1 = 0.f;
#pragma unroll
        for (int j = 0; j < 8; j++) {
            float p0 = exp2f(s[j][0] - mn0);
            float p1 = exp2f(s[j][1] - mn0);
            float p2 = exp2f(s[j][2] - mn1);
            float p3 = exp2f(s[j][3] - mn1);
            rs0 += p0 + p1;
            rs1 += p2 + p3;
            float2 lo = make_float2(__uint_as_float(f2tf(p0)), __uint_as_float(f2tf(p1)));
            float2 hi = make_float2(__uint_as_float(f2tf(p2)), __uint_as_float(f2tf(p3)));
            *(float2*)(sP + g * PSTR + j * 8 + 2 * t)       = lo;
            *(float2*)(sP + (g + 8) * PSTR + j * 8 + 2 * t) = hi;
        }
        rs0 += __shfl_xor_sync(0xffffffffu, rs0, 1);
        rs0 += __shfl_xor_sync(0xffffffffu, rs0, 2);
        rs1 += __shfl_xor_sync(0xffffffffu, rs1, 1);
        rs1 += __shfl_xor_sync(0xffffffffu, rs1, 2);

        l0 = l0 * fac0 + rs0;
        l1 = l1 * fac1 + rs1;
        m0 = mn0;
        m1 = mn1;
#pragma unroll
        for (int j = 0; j < 8; j++) {
            o[j][0] *= fac0; o[j][1] *= fac0;
            o[j][2] *= fac1; o[j][3] *= fac1;
        }

        __syncwarp();   // sP writes -> reads (warp-private tile)

        // ---- O += P * V ----
#pragma unroll
        for (int kk = 0; kk < 8; kk++) {
            const int pa = g * PSTR + kk * 8 + t;
            const int pb = (g + 8) * PSTR + kk * 8 + t;
            unsigned a0 = __float_as_uint(sP[pa]);
            unsigned a1 = __float_as_uint(sP[pb]);
            unsigned a2 = __float_as_uint(sP[pa + 4]);
            unsigned a3 = __float_as_uint(sP[pb + 4]);
#pragma unroll
            for (int j = 0; j < 8; j++) {
                unsigned b0 = __float_as_uint(sV[(kk * 8 + t) * VSTR + j * 8 + g]);
                unsigned b1 = __float_as_uint(sV[(kk * 8 + t + 4) * VSTR + j * 8 + g]);
                mma_tf32(o[j], a0, a1, a2, a3, b0, b1);
            }
        }
    }

    // ---- epilogue: normalize and store ----
    const float il0 = 1.0f / l0;
    const float il1 = 1.0f / l1;
#pragma unroll
    for (int j = 0; j < 8; j++) {
        float2 lo = make_float2(o[j][0] * il0, o[j][1] * il0);
        float2 hi = make_float2(o[j][2] * il1, o[j][3] * il1);
        *(float2*)(Ob + (size_t)qrow * DDIM + j * 8 + 2 * t)       = lo;
        *(float2*)(Ob + (size_t)(qrow + 8) * DDIM + j * 8 + 2 * t) = hi;
    }
}

extern "C" void kernel_launch(void* const* d_in, const int* in_sizes, int n_in,
                              void* d_out, int out_size) {
    const float* Q = (const float*)d_in[0];
    const float* K = (const float*)d_in[1];
    const float* V = (const float*)d_in[2];
    float* O = (float*)d_out;

    cudaFuncSetAttribute(sdpa_tf32_kernel,
                         cudaFuncAttributeMaxDynamicSharedMemorySize, SMEM_BYTES);

    dim3 grid(SEQ / BM, NBH);   // (16, 64) = 1024 CTAs
    sdpa_tf32_kernel<<<grid, NTHR, SMEM_BYTES>>>(Q, K, V, O);
}